// round 9
// baseline (speedup 1.0000x reference)
#include <cuda_runtime.h>
#include <cuda_bf16.h>

// Problem constants:
//   bs=4, c=3, dsrc=1, h=w=128, d=8, K=10 -> K1=11, out_channels=66
//   out shape (bs, 66, d, h, w) float32
#define BS   4
#define CCH  3
#define HH   128
#define WW   128
#define DD   8
#define KK   10
#define K1   (KK + 1)
#define HW   (HH * WW)          // 16384
#define NREST (BS * DD * K1)    // 352

// uniform-r 5-element window select out of two float4s (r uniform per block)
__device__ __forceinline__ void sel5(const float4& qa, const float4& qb, int r,
                                     float* o) {
    switch (r) {
        case 0:  o[0]=qa.x; o[1]=qa.y; o[2]=qa.z; o[3]=qa.w; o[4]=qb.x; break;
        case 1:  o[0]=qa.y; o[1]=qa.z; o[2]=qa.w; o[3]=qb.x; o[4]=qb.y; break;
        case 2:  o[0]=qa.z; o[1]=qa.w; o[2]=qb.x; o[3]=qb.y; o[4]=qb.z; break;
        default: o[0]=qa.w; o[1]=qb.x; o[2]=qb.y; o[3]=qb.z; o[4]=qb.w; break;
    }
}

// ---------------------------------------------------------------------------
// Single fused kernel. One block = one (b, dd, k1) x 16 y-rows; one thread =
// 8 consecutive x pixels of one row.
// Phase 1 (per block): separable gaussian tables ex[128], ey[128] in smem +
//   sums Sx, Sy (2D sum factorizes: sum2d = Sx*Sy).
// Phase 2: 12 float4 stores per thread:
//   heat = ex[x]*ey[y]/(Sx*Sy), diffx, diffy (constants),
//   3 channels of source bilinearly sampled at the constant per-block shift.
// Gather: the block-uniform misalignment r = floor(sx)&3 lets each thread
// cover its 9-column window with three aligned float4 loads + uniform select.
// Clamped loads only ever carry fully out-of-range column labels -> the
// zero-mask by true column index is exact.
// ---------------------------------------------------------------------------
__global__ __launch_bounds__(256)
void movement_embed_kernel(const float* __restrict__ src,
                           const float* __restrict__ kp_drv,
                           const float* __restrict__ kp_src,
                           float* __restrict__ out) {
    const int t    = threadIdx.x;              // 0..255
    const int rest = blockIdx.x >> 3;          // 0..351  (b,dd,k1)
    const int yhi  = blockIdx.x & 7;
    const int xo   = t & 15;                   // x octet: x = xo*8 .. xo*8+7
    const int y    = (yhi << 4) | (t >> 4);
    const int xb   = xo << 3;

    const int k1 = rest % K1;
    const int bd = rest / K1;                  // b*8 + dd
    const int b  = bd >> 3;

    float mx = 0.0f, my = 0.0f, diffx = 0.0f, diffy = 0.0f;
    if (k1 > 0) {
        const int kidx = bd * KK + (k1 - 1);
        mx = kp_drv[2 * kidx + 0];
        my = kp_drv[2 * kidx + 1];
        diffx = kp_src[2 * kidx + 0] - mx;
        diffy = kp_src[2 * kidx + 1] - my;
    }

    // ---- phase 1: per-block separable tables (tab[0..127]=ex, [128..255]=ey)
    __shared__ float tab[256];
    __shared__ float red[8];
    {
        const float g = (float)(t & 127) * (2.0f / (WW - 1)) - 1.0f;
        const float m = (t < 128) ? mx : my;
        const float dg = g - m;
        const float e = __expf(-50.0f * dg * dg);   // -0.5/0.01
        tab[t] = e;
        float s = e;
        #pragma unroll
        for (int off = 16; off > 0; off >>= 1)
            s += __shfl_xor_sync(0xFFFFFFFFu, s, off);
        if ((t & 31) == 0) red[t >> 5] = s;
    }
    __syncthreads();
    const float Sx = red[0] + red[1] + red[2] + red[3];
    const float Sy = red[4] + red[5] + red[6] + red[7];
    const float inv = 1.0f / (Sx * Sy);

    float4 heatA = make_float4(0.f, 0.f, 0.f, 0.f);
    float4 heatB = make_float4(0.f, 0.f, 0.f, 0.f);
    if (k1 > 0) {
        const float eyv = tab[128 + y] * inv;
        const float4 exa = *(const float4*)&tab[xb];
        const float4 exb = *(const float4*)&tab[xb + 4];
        heatA = make_float4(exa.x * eyv, exa.y * eyv, exa.z * eyv, exa.w * eyv);
        heatB = make_float4(exb.x * eyv, exb.y * eyv, exb.z * eyv, exb.w * eyv);
    }

    // ---- phase 2: bilinear sample at constant pixel shift, zero padding ----
    const float sx = diffx * (0.5f * (WW - 1));   // * 63.5
    const float sy = diffy * (0.5f * (HH - 1));

    const float py  = (float)y + sy;
    const float fy  = floorf(py);
    const int   iy0 = (int)fy, iy1 = iy0 + 1;
    const float wy1 = py - fy, wy0 = 1.0f - wy1;
    const float wy0v = wy0 * (((unsigned)iy0 < (unsigned)HH) ? 1.0f : 0.0f);
    const float wy1v = wy1 * (((unsigned)iy1 < (unsigned)HH) ? 1.0f : 0.0f);
    const int cy0 = min(max(iy0, 0), HH - 1);
    const int cy1 = min(max(iy1, 0), HH - 1);

    const float fsx = floorf(sx);
    const int   isx = (int)fsx;
    const float wx1 = sx - fsx, wx0 = 1.0f - wx1;
    const int   r   = isx & 3;                    // uniform per block
    const int   ix0 = xb + isx;                   // first needed column
    const int   B   = xb + (isx & ~3);            // aligned window base
    const int   o0  = min(max(B,     0), WW - 4);
    const int   o1  = min(max(B + 4, 0), WW - 4);
    const int   o2  = min(max(B + 8, 0), WW - 4);

    float amask[9];
    #pragma unroll
    for (int j = 0; j < 9; j++)
        amask[j] = ((unsigned)(ix0 + j) < (unsigned)WW) ? 1.0f : 0.0f;

    // ---- output addressing ----
    const int chs  = DD * HW;
    const int base = ((b * (K1 * 6) + k1 * 6) * DD + (bd & (DD - 1))) * HW
                     + (y << 7) + xb;
    float* o = out + base;

    *(float4*)(o)               = heatA;
    *(float4*)(o + 4)           = heatB;
    *(float4*)(o + chs)         = make_float4(diffx, diffx, diffx, diffx);
    *(float4*)(o + chs + 4)     = make_float4(diffx, diffx, diffx, diffx);
    *(float4*)(o + 2 * chs)     = make_float4(diffy, diffy, diffy, diffy);
    *(float4*)(o + 2 * chs + 4) = make_float4(diffy, diffy, diffy, diffy);

    const float* im = src + b * (CCH * HW);
    #pragma unroll
    for (int cc = 0; cc < CCH; cc++) {
        const float* r0p = im + cc * HW + (cy0 << 7);
        const float* r1p = im + cc * HW + (cy1 << 7);
        const float4 q00 = *(const float4*)(r0p + o0);
        const float4 q01 = *(const float4*)(r0p + o1);
        const float4 q02 = *(const float4*)(r0p + o2);
        const float4 q10 = *(const float4*)(r1p + o0);
        const float4 q11 = *(const float4*)(r1p + o1);
        const float4 q12 = *(const float4*)(r1p + o2);

        float a0[9], a1[9];
        sel5(q00, q01, r, a0);
        sel5(q01, q02, r, a0 + 4);   // overlaps a0[4]; same value
        sel5(q10, q11, r, a1);
        sel5(q11, q12, r, a1 + 4);
        #pragma unroll
        for (int j = 0; j < 9; j++) { a0[j] *= amask[j]; a1[j] *= amask[j]; }

        float v[8];
        #pragma unroll
        for (int i = 0; i < 8; i++)
            v[i] = wy0v * (wx0 * a0[i] + wx1 * a0[i + 1])
                 + wy1v * (wx0 * a1[i] + wx1 * a1[i + 1]);
        *(float4*)(o + (3 + cc) * chs)     = make_float4(v[0], v[1], v[2], v[3]);
        *(float4*)(o + (3 + cc) * chs + 4) = make_float4(v[4], v[5], v[6], v[7]);
    }
}

// ---------------------------------------------------------------------------
extern "C" void kernel_launch(void* const* d_in, const int* in_sizes, int n_in,
                              void* d_out, int out_size) {
    const float* src    = (const float*)d_in[0];  // (4,3,1,128,128)
    const float* kp_drv = (const float*)d_in[1];  // (4,8,10,2)
    const float* kp_src = (const float*)d_in[2];  // (4,8,10,2)
    float* out = (float*)d_out;                   // (4,66,8,128,128)

    // 352 (b,dd,k1) groups x 8 y-slabs = 2816 blocks of 256 threads
    movement_embed_kernel<<<NREST * 8, 256>>>(src, kp_drv, kp_src, out);
}